// round 9
// baseline (speedup 1.0000x reference)
#include <cuda_runtime.h>
#include <cuda_fp16.h>
#include <math.h>
#include <stdint.h>

#define NN   8192
#define SQ   4
#define DIM  512
#define NH   4
#define DH   128
#define ET   73728
#define BOUT 128
#define NCHUNK 8
#define CH_ROWS ((SQ * ET) / NCHUNK)   // 36864, multiple of 128

// ---------------- scratch (device globals; no runtime alloc allowed) -------
__device__ float  g_node_raw[NN * 8];
__device__ float  g_node_pos[NN * DIM];
__device__ __half g_Xth[NN * DIM];
__device__ __half g_Xh [(size_t)SQ * NN * DIM];
__device__ float  g_Xout[(size_t)SQ * NN * DIM];
__device__ __half g_QKVh[(size_t)SQ * NN * 3 * DIM];
__device__ __half g_ehh [(size_t)ET * DIM];
__device__ __half g_e0h [(size_t)ET * DIM];
__device__ __half g_e1h [(size_t)SQ * ET * DIM];
__device__ __half g_Ew1h[(size_t)ET * 2 * DIM];
__device__ __half g_Ew2h[(size_t)SQ * ET * 2 * DIM];
__device__ float  g_logits[SQ * ET * NH];
__device__ float  g_m[SQ * NN * NH];
__device__ float  g_z[SQ * NN * NH];
__device__ __half g_Wpackth[2 * 3 * DIM * DIM];
__device__ __half g_wn2th[DIM * DIM];
__device__ __half g_wp2th[DIM * DIM];
__device__ __half g_WEth[2 * 2 * DIM * DIM];

// ---------------- small utility kernels ------------------------------------
__global__ void kzero(float* __restrict__ p, size_t n) {
    size_t i = (size_t)blockIdx.x * blockDim.x + threadIdx.x;
    if (i < n) p[i] = 0.f;
}

__global__ void k_tohalf(const float* __restrict__ s, __half* __restrict__ d, size_t n) {
    size_t i = (size_t)blockIdx.x * blockDim.x + threadIdx.x;
    if (i < n) d[i] = __float2half_rn(s[i]);
}

__global__ void k_selfloop(const int* __restrict__ ei, const float* __restrict__ emb) {
    int e = blockIdx.x * blockDim.x + threadIdx.x;
    if (e >= ET) return;
    int s = ei[e], d = ei[ET + e];
    if (s == d) {
        #pragma unroll
        for (int r = 0; r < 8; r++)
            atomicAdd(&g_node_raw[s * 8 + r], emb[e * 8 + r]);
    }
}

__global__ void k_mlp1h(const float* __restrict__ in, const float* __restrict__ w1,
                        const float* __restrict__ b1, __half* __restrict__ out, int rows) {
    long long idx = (long long)blockIdx.x * blockDim.x + threadIdx.x;
    if (idx >= (long long)rows * DIM) return;
    int n = (int)(idx >> 9), j = (int)(idx & 511);
    const float* ip = in + (long long)n * 8;
    float acc = b1[j];
    #pragma unroll
    for (int r = 0; r < 8; r++) acc = fmaf(ip[r], w1[r * DIM + j], acc);
    out[idx] = __float2half_rn(fmaxf(acc, 0.f));
}

__global__ void k_add(const float* __restrict__ query, const float* __restrict__ npos,
                      __half* __restrict__ X) {
    size_t idx = (size_t)blockIdx.x * blockDim.x + threadIdx.x;
    if (idx >= (size_t)SQ * NN * DIM) return;
    int j = (int)(idx & 511);
    int n = (int)((idx >> 9) % NN);
    int s = (int)(idx / ((size_t)NN * DIM));
    X[idx] = __float2half_rn(query[(size_t)n * SQ * DIM + (size_t)s * DIM + j] +
                             npos[(size_t)n * DIM + j]);
}

__global__ void k_gather(const float* __restrict__ X, const int* __restrict__ mapping,
                         float* __restrict__ out) {
    int idx = blockIdx.x * blockDim.x + threadIdx.x;
    if (idx >= BOUT * SQ * DIM) return;
    int j = idx & 511;
    int s = (idx >> 9) & 3;
    int b = idx >> 11;
    out[idx] = X[((size_t)s * NN + mapping[b]) * DIM + j];
}

__global__ void k_transposeTh(const float* __restrict__ W, __half* __restrict__ Wt, int Nw) {
    int idx = blockIdx.x * blockDim.x + threadIdx.x;
    if (idx >= Nw * 512) return;
    int k = idx & 511;
    int n = idx >> 9;
    Wt[idx] = __float2half_rn(W[(size_t)k * Nw + n]);
}

__global__ void k_packwTh(const float* __restrict__ WQ, const float* __restrict__ WK,
                          const float* __restrict__ WV) {
    int idx = blockIdx.x * blockDim.x + threadIdx.x;
    if (idx >= 2 * 1536 * 512) return;
    int k = idx & 511;
    int n = (idx >> 9) % 1536;
    int l = idx / (1536 * 512);
    const float* W = (n < 512) ? WQ : ((n < 1024) ? WK : WV);
    int nn = n & 511;
    g_Wpackth[idx] = __float2half_rn(W[(size_t)l * 512 * 512 + (size_t)k * 512 + nn]);
}

// ---------------- fp16 tensor-core GEMM (ldmatrix fragments) ----------------
#define BKH     32
#define KTOT    512
#define KSTEPS  (KTOT / BKH)
#define STG     3
#define STRH    40
#define OP_HALVES (128 * STRH)
#define GEMM_SMEM (STG * 2 * OP_HALVES * 2)

__device__ __forceinline__ void cp16(uint32_t dst, const void* src) {
    asm volatile("cp.async.cg.shared.global [%0], [%1], 16;\n" :: "r"(dst), "l"(src));
}
__device__ __forceinline__ void cp_commit() { asm volatile("cp.async.commit_group;\n"); }
__device__ __forceinline__ void cp_wait1()  { asm volatile("cp.async.wait_group 1;\n"); }

__device__ __forceinline__ void ldsm4(uint32_t& r0, uint32_t& r1, uint32_t& r2,
                                      uint32_t& r3, uint32_t addr) {
    asm volatile("ldmatrix.sync.aligned.m8n8.x4.shared.b16 {%0,%1,%2,%3}, [%4];"
                 : "=r"(r0), "=r"(r1), "=r"(r2), "=r"(r3) : "r"(addr));
}

__device__ __forceinline__ void mma_f16(float& c0, float& c1, float& c2, float& c3,
                                        uint32_t a0, uint32_t a1, uint32_t a2, uint32_t a3,
                                        uint32_t b0, uint32_t b1) {
    asm volatile("mma.sync.aligned.m16n8k16.row.col.f32.f16.f16.f32 "
                 "{%0,%1,%2,%3}, {%4,%5,%6,%7}, {%8,%9}, {%0,%1,%2,%3};\n"
                 : "+f"(c0), "+f"(c1), "+f"(c2), "+f"(c3)
                 : "r"(a0), "r"(a1), "r"(a2), "r"(a3), "r"(b0), "r"(b1));
}

__global__ void __launch_bounds__(256, 2)
gemm_h(const __half* __restrict__ A, const __half* __restrict__ Bt,
       const float* __restrict__ bias, void* __restrict__ Cout,
       int M, int N, int halfOut) {
    extern __shared__ __half sh[];
    __half* Abase = sh;
    __half* Bbase = sh + STG * OP_HALVES;

    const int tid  = threadIdx.x;
    const int lane = tid & 31;
    const int warp = tid >> 5;
    const int wm = warp & 1;
    const int wn = warp >> 1;
    const int g  = lane >> 2;
    const int t  = lane & 3;

    const long long bRow = (long long)blockIdx.y * 128;
    const long long bCol = (long long)blockIdx.x * 128;

    int rowL[2], cL[2];
    #pragma unroll
    for (int i = 0; i < 2; i++) {
        int ch = tid * 2 + i;
        rowL[i] = ch >> 2;
        cL[i]   = ch & 3;
    }
    const uint32_t suA = (uint32_t)__cvta_generic_to_shared(Abase);
    const uint32_t suB = (uint32_t)__cvta_generic_to_shared(Bbase);
    uint32_t aD[2], bD[2];
    #pragma unroll
    for (int i = 0; i < 2; i++) {
        aD[i] = suA + (uint32_t)(rowL[i] * STRH + cL[i] * 8) * 2u;
        bD[i] = suB + (uint32_t)(rowL[i] * STRH + cL[i] * 8) * 2u;
    }
    const __half* Ag[2];
    const __half* Bg[2];
    #pragma unroll
    for (int i = 0; i < 2; i++) {
        Ag[i] = A  + (bRow + rowL[i]) * (long long)KTOT + cL[i] * 8;
        Bg[i] = Bt + (bCol + rowL[i]) * (long long)KTOT + cL[i] * 8;
    }

    const uint32_t laneAoff = (uint32_t)(((lane & 7) + ((lane >> 3) & 1) * 8) * STRH
                                         + (lane >> 4) * 8);
    const uint32_t laneBoff = (uint32_t)(((lane & 7) + (lane >> 4) * 8) * STRH
                                         + ((lane >> 3) & 1) * 8);

    float acc[4][4][4];
    #pragma unroll
    for (int mt = 0; mt < 4; mt++)
        #pragma unroll
        for (int nt = 0; nt < 4; nt++)
            #pragma unroll
            for (int q = 0; q < 4; q++) acc[mt][nt][q] = 0.f;

    #pragma unroll
    for (int s = 0; s < 2; s++) {
        #pragma unroll
        for (int i = 0; i < 2; i++) {
            cp16(aD[i] + (uint32_t)(s * OP_HALVES * 2), Ag[i] + s * BKH);
            cp16(bD[i] + (uint32_t)(s * OP_HALVES * 2), Bg[i] + s * BKH);
        }
        cp_commit();
    }

    for (int kt = 0; kt < KSTEPS; kt++) {
        cp_wait1();
        __syncthreads();

        if (kt + 2 < KSTEPS) {
            const int st = (kt + 2) % STG;
            #pragma unroll
            for (int i = 0; i < 2; i++) {
                cp16(aD[i] + (uint32_t)(st * OP_HALVES * 2), Ag[i] + (kt + 2) * BKH);
                cp16(bD[i] + (uint32_t)(st * OP_HALVES * 2), Bg[i] + (kt + 2) * BKH);
            }
        }
        cp_commit();

        const uint32_t Ab = suA + (uint32_t)((kt % STG) * OP_HALVES) * 2u;
        const uint32_t Bb = suB + (uint32_t)((kt % STG) * OP_HALVES) * 2u;

        #pragma unroll
        for (int kk = 0; kk < BKH; kk += 16) {
            uint32_t af[4][4], bf[4][2];
            #pragma unroll
            for (int mt = 0; mt < 4; mt++) {
                uint32_t addr = Ab + 2u * (laneAoff + (uint32_t)((wm * 64 + mt * 16) * STRH + kk));
                ldsm4(af[mt][0], af[mt][1], af[mt][2], af[mt][3], addr);
            }
            #pragma unroll
            for (int p = 0; p < 2; p++) {
                uint32_t addr = Bb + 2u * (laneBoff + (uint32_t)((wn * 32 + p * 16) * STRH + kk));
                ldsm4(bf[2 * p][0], bf[2 * p][1], bf[2 * p + 1][0], bf[2 * p + 1][1], addr);
            }
            #pragma unroll
            for (int mt = 0; mt < 4; mt++)
                #pragma unroll
                for (int nt = 0; nt < 4; nt++)
                    mma_f16(acc[mt][nt][0], acc[mt][nt][1], acc[mt][nt][2], acc[mt][nt][3],
                            af[mt][0], af[mt][1], af[mt][2], af[mt][3],
                            bf[nt][0], bf[nt][1]);
        }
        __syncthreads();
    }

    #pragma unroll
    for (int mt = 0; mt < 4; mt++) {
        #pragma unroll
        for (int nt = 0; nt < 4; nt++) {
            long long row0 = bRow + wm * 64 + mt * 16 + g;
            long long col  = bCol + wn * 32 + nt * 8 + t * 2;
            float b0 = 0.f, b1 = 0.f;
            if (bias) { b0 = bias[col]; b1 = bias[col + 1]; }
            float v00 = acc[mt][nt][0] + b0, v01 = acc[mt][nt][1] + b1;
            float v10 = acc[mt][nt][2] + b0, v11 = acc[mt][nt][3] + b1;
            if (halfOut) {
                __half2* C = (__half2*)Cout;
                C[(row0 * N + col) >> 1]       = __floats2half2_rn(v00, v01);
                C[((row0 + 8) * N + col) >> 1] = __floats2half2_rn(v10, v11);
            } else {
                float* C = (float*)Cout;
                *(float2*)(C + row0 * N + col)       = make_float2(v00, v01);
                *(float2*)(C + (row0 + 8) * N + col) = make_float2(v10, v11);
            }
        }
    }
}

// ---------------- softmax helpers -------------------------------------------
__device__ __forceinline__ void atomicMaxF(float* addr, float val) {
    int* ia = (int*)addr;
    int old = *ia;
    while (__int_as_float(old) < val) {
        int assumed = old;
        old = atomicCAS(ia, assumed, __float_as_int(val));
        if (old == assumed) break;
    }
}

__global__ void k_initmz() {
    int i = blockIdx.x * blockDim.x + threadIdx.x;
    if (i < SQ * NN * NH) { g_m[i] = __int_as_float(0xff800000); g_z[i] = 0.f; }
}

// ---------------- layer-0 edge kernel: warp per (e,h), loops s --------------
// Ew1 is position-invariant: fragment loaded once into registers, reused 4x.
__global__ void k_edge0(const __half* __restrict__ QKV,
                        const int* __restrict__ src, const int* __restrict__ dst,
                        const __half* __restrict__ Ew,
                        const float* __restrict__ aw, __half* __restrict__ e_out) {
    int w = (blockIdx.x * blockDim.x + threadIdx.x) >> 5;
    int lane = threadIdx.x & 31;
    if (w >= ET * NH) return;
    int e = w >> 2, h = w & 3;
    int sn = src[e], dn = dst[e];

    const __half2* ewp = (const __half2*)(Ew + (size_t)e * (2 * DIM) + h * 256);
    __half2 ew[2], eb[2];
    float a0[2], a1[2];
    #pragma unroll
    for (int i = 0; i < 2; i++) {
        int dd = lane + 32 * i;
        ew[i] = ewp[dd];
        eb[i] = ewp[dd + 64];
        a0[i] = aw[h * DH + 2 * dd];
        a1[i] = aw[h * DH + 2 * dd + 1];
    }

    #pragma unroll
    for (int s = 0; s < SQ; s++) {
        const __half2* qp = (const __half2*)(QKV + ((size_t)s * NN + dn) * (3 * DIM) + h * DH);
        const __half2* kp = (const __half2*)(QKV + ((size_t)s * NN + sn) * (3 * DIM) + DIM + h * DH);
        __half2* op = (__half2*)(e_out + ((size_t)s * ET + e) * DIM + h * DH);
        float lg = 0.f;
        #pragma unroll
        for (int i = 0; i < 2; i++) {
            int dd = lane + 32 * i;
            float2 kq = __half22float2(__hadd2(kp[dd], qp[dd]));
            float2 ewf = __half22float2(ew[i]);
            float2 ebf = __half22float2(eb[i]);
            float t0 = kq.x * ewf.x, t1 = kq.y * ewf.y;
            float s0 = (t0 >= 0.f) ? sqrtf(t0) : -sqrtf(-t0);
            float s1 = (t1 >= 0.f) ? sqrtf(t1) : -sqrtf(-t1);
            s0 = fmaxf(s0 + ebf.x, 0.f);
            s1 = fmaxf(s1 + ebf.y, 0.f);
            op[dd] = __floats2half2_rn(s0, s1);
            lg = fmaf(s0, a0[i], lg);
            lg = fmaf(s1, a1[i], lg);
        }
        #pragma unroll
        for (int off = 16; off; off >>= 1) lg += __shfl_xor_sync(0xffffffffu, lg, off);
        if (lane == 0) {
            g_logits[((size_t)s * ET + e) * NH + h] = lg;
            atomicMaxF(&g_m[(s * NN + dn) * NH + h], lg);
        }
    }
}

// ---------------- layer-1 edge kernel: warp per row-chunk entry -------------
__global__ void k_edge1(const __half* __restrict__ QKV,
                        const int* __restrict__ src, const int* __restrict__ dst,
                        const __half* __restrict__ Ew, int baseRow,
                        const float* __restrict__ aw) {
    int w = (blockIdx.x * blockDim.x + threadIdx.x) >> 5;
    int lane = threadIdx.x & 31;
    if (w >= CH_ROWS * NH) return;
    int row = baseRow + (w >> 2);
    int h = w & 3;
    int s = row / ET;
    int e = row % ET;
    int sn = src[e], dn = dst[e];
    const __half2* qp  = (const __half2*)(QKV + ((size_t)s * NN + dn) * (3 * DIM) + h * DH);
    const __half2* kp  = (const __half2*)(QKV + ((size_t)s * NN + sn) * (3 * DIM) + DIM + h * DH);
    const __half2* ewp = (const __half2*)(Ew + (size_t)row * (2 * DIM) + h * 256);
    float lg = 0.f;
    #pragma unroll
    for (int i = 0; i < 2; i++) {
        int dd = lane + 32 * i;
        float2 kq = __half22float2(__hadd2(kp[dd], qp[dd]));
        float2 ewf = __half22float2(ewp[dd]);
        float2 ebf = __half22float2(ewp[dd + 64]);
        float t0 = kq.x * ewf.x, t1 = kq.y * ewf.y;
        float s0 = (t0 >= 0.f) ? sqrtf(t0) : -sqrtf(-t0);
        float s1 = (t1 >= 0.f) ? sqrtf(t1) : -sqrtf(-t1);
        s0 = fmaxf(s0 + ebf.x, 0.f);
        s1 = fmaxf(s1 + ebf.y, 0.f);
        lg = fmaf(s0, aw[h * DH + 2 * dd], lg);
        lg = fmaf(s1, aw[h * DH + 2 * dd + 1], lg);
    }
    #pragma unroll
    for (int off = 16; off; off >>= 1) lg += __shfl_xor_sync(0xffffffffu, lg, off);
    if (lane == 0) {
        g_logits[(size_t)row * NH + h] = lg;
        atomicMaxF(&g_m[(s * NN + dn) * NH + h], lg);
    }
}

__global__ void k_expsum(const int* __restrict__ dst) {
    int i = blockIdx.x * blockDim.x + threadIdx.x;
    if (i >= SQ * ET * NH) return;
    int s = i / (ET * NH);
    int r = i % (ET * NH);
    int e = r >> 2, h = r & 3;
    float wv = expf(g_logits[i] - g_m[(s * NN + dst[e]) * NH + h]);
    g_logits[i] = wv;
    atomicAdd(&g_z[(s * NN + dst[e]) * NH + h], wv);
}

__global__ void k_msg(const __half* __restrict__ QKV, const int* __restrict__ src,
                      const int* __restrict__ dst, float* __restrict__ xout) {
    long long w = ((long long)blockIdx.x * blockDim.x + threadIdx.x) >> 5;
    int lane = threadIdx.x & 31;
    if (w >= (long long)SQ * ET * NH) return;
    int s = (int)(w / (ET * NH));
    int r = (int)(w % (ET * NH));
    int e = r >> 2, h = r & 3;
    int sn = src[e], dn = dst[e];
    float alpha = g_logits[(size_t)s * ET * NH + e * NH + h] /
                  (g_z[(s * NN + dn) * NH + h] + 1e-16f);
    const __half2* vp = (const __half2*)(QKV + ((size_t)s * NN + sn) * (3 * DIM)
                                         + 2 * DIM + h * DH);
    float* op = xout + ((size_t)s * NN + dn) * DIM + h * DH;
    #pragma unroll
    for (int i = 0; i < 2; i++) {
        int dd = lane + 32 * i;
        float2 v = __half22float2(vp[dd]);
        atomicAdd(&op[2 * dd],     v.x * alpha);
        atomicAdd(&op[2 * dd + 1], v.y * alpha);
    }
}

// ---------------- host orchestration ---------------------------------------
extern "C" void kernel_launch(void* const* d_in, const int* in_sizes, int n_in,
                              void* d_out, int out_size) {
    const float* query   = (const float*)d_in[0];
    const int*   ei      = (const int*)  d_in[1];
    const int*   mapping = (const int*)  d_in[2];
    const float* emb     = (const float*)d_in[3];
    const float* wn_w1 = (const float*)d_in[5];
    const float* wn_b1 = (const float*)d_in[6];
    const float* wn_w2 = (const float*)d_in[7];
    const float* wn_b2 = (const float*)d_in[8];
    const float* wp_w1 = (const float*)d_in[9];
    const float* wp_b1 = (const float*)d_in[10];
    const float* wp_w2 = (const float*)d_in[11];
    const float* wp_b2 = (const float*)d_in[12];
    const float* WQ    = (const float*)d_in[13];
    const float* WK    = (const float*)d_in[14];
    const float* WV    = (const float*)d_in[15];
    const float* WE    = (const float*)d_in[16];
    const float* bE    = (const float*)d_in[17];
    const float* Aw    = (const float*)d_in[18];
    float* out = (float*)d_out;

    float  *node_raw, *node_pos, *Xout;
    __half *Xth, *Xh, *QKVh, *ehh, *e0h, *e1h, *Ew1h, *Ew2h;
    __half *Wpackth, *wn2th, *wp2th, *WEth;
    cudaGetSymbolAddress((void**)&node_raw, g_node_raw);
    cudaGetSymbolAddress((void**)&node_pos, g_node_pos);
    cudaGetSymbolAddress((void**)&Xth,  g_Xth);
    cudaGetSymbolAddress((void**)&Xh,   g_Xh);
    cudaGetSymbolAddress((void**)&Xout, g_Xout);
    cudaGetSymbolAddress((void**)&QKVh, g_QKVh);
    cudaGetSymbolAddress((void**)&ehh,  g_ehh);
    cudaGetSymbolAddress((void**)&e0h,  g_e0h);
    cudaGetSymbolAddress((void**)&e1h,  g_e1h);
    cudaGetSymbolAddress((void**)&Ew1h, g_Ew1h);
    cudaGetSymbolAddress((void**)&Ew2h, g_Ew2h);
    cudaGetSymbolAddress((void**)&Wpackth, g_Wpackth);
    cudaGetSymbolAddress((void**)&wn2th, g_wn2th);
    cudaGetSymbolAddress((void**)&wp2th, g_wp2th);
    cudaGetSymbolAddress((void**)&WEth,  g_WEth);

    cudaFuncSetAttribute(gemm_h, cudaFuncAttributeMaxDynamicSharedMemorySize, GEMM_SMEM);

    const int* srcp = ei;
    const int* dstp = ei + ET;
    const int T = 256;

    // ---- fp16 weight packs (tiny) ----
    k_transposeTh<<<(512 * 512) / T, T>>>(wn_w2, wn2th, 512);
    k_transposeTh<<<(512 * 512) / T, T>>>(wp_w2, wp2th, 512);
    k_transposeTh<<<(1024 * 512) / T, T>>>(WE, WEth, 1024);
    k_transposeTh<<<(1024 * 512) / T, T>>>(WE + 512 * 1024, WEth + 1024 * 512, 1024);
    k_packwTh<<<(2 * 1536 * 512) / T, T>>>(WQ, WK, WV);

    // ---- position-invariant precompute ----
    kzero<<<(NN * 8 + T - 1) / T, T>>>(node_raw, NN * 8);
    k_selfloop<<<(ET + T - 1) / T, T>>>(ei, emb);
    k_mlp1h<<<(NN * DIM) / T, T>>>(node_raw, wn_w1, wn_b1, Xth, NN);
    gemm_h<<<dim3(DIM / 128, NN / 128), T, GEMM_SMEM>>>(Xth, wn2th, wn_b2, node_pos,
                                                        NN, DIM, 0);
    k_mlp1h<<<(ET * DIM) / T, T>>>(emb, wp_w1, wp_b1, ehh, ET);
    gemm_h<<<dim3(DIM / 128, ET / 128), T, GEMM_SMEM>>>(ehh, wp2th, wp_b2, e0h,
                                                        ET, DIM, 1);
    gemm_h<<<dim3((2 * DIM) / 128, ET / 128), T, GEMM_SMEM>>>(e0h, WEth, bE, Ew1h,
                                                              ET, 2 * DIM, 1);

    // ---- batched positions ----
    k_add<<<(SQ * NN * DIM) / T, T>>>(query, node_pos, Xh);

    const long long edgeWarps = (long long)SQ * ET * NH;
    const int msgWarpBlocks = (int)((edgeWarps * 32) / T);
    const int ehBlocks = (int)(edgeWarps / T);

    // ======== layer 0 ========
    gemm_h<<<dim3((3 * DIM) / 128, (SQ * NN) / 128), T, GEMM_SMEM>>>(
        Xh, Wpackth, nullptr, QKVh, SQ * NN, 3 * DIM, 1);
    k_initmz<<<(SQ * NN * NH + T - 1) / T, T>>>();
    k_edge0<<<(ET * NH * 32) / T, T>>>(QKVh, srcp, dstp, Ew1h, Aw, e1h);
    k_expsum<<<ehBlocks, T>>>(dstp);
    kzero<<<((size_t)SQ * NN * DIM + T - 1) / T, T>>>(Xout, (size_t)SQ * NN * DIM);
    k_msg<<<msgWarpBlocks, T>>>(QKVh, srcp, dstp, Xout);
    k_tohalf<<<((size_t)SQ * NN * DIM + T - 1) / T, T>>>(Xout, Xh, (size_t)SQ * NN * DIM);

    // ======== layer 1 ========
    gemm_h<<<dim3((3 * DIM) / 128, (SQ * NN) / 128), T, GEMM_SMEM>>>(
        Xh, Wpackth + (size_t)1536 * 512, nullptr, QKVh, SQ * NN, 3 * DIM, 1);
    k_initmz<<<(SQ * NN * NH + T - 1) / T, T>>>();
    // chunked: Ew2 chunk stays L2-resident between producer GEMM and consumer k_edge1
    for (int c = 0; c < NCHUNK; c++) {
        size_t base = (size_t)c * CH_ROWS;
        gemm_h<<<dim3((2 * DIM) / 128, CH_ROWS / 128), T, GEMM_SMEM>>>(
            e1h + base * 512, WEth + 1024 * 512, bE + 2 * DIM,
            Ew2h + base * 1024, CH_ROWS, 2 * DIM, 1);
        k_edge1<<<(CH_ROWS * NH * 32) / T, T>>>(QKVh, srcp, dstp, Ew2h, (int)base,
                                                Aw + DIM);
    }
    k_expsum<<<ehBlocks, T>>>(dstp);
    kzero<<<((size_t)SQ * NN * DIM + T - 1) / T, T>>>(Xout, (size_t)SQ * NN * DIM);
    k_msg<<<msgWarpBlocks, T>>>(QKVh, srcp, dstp, Xout);

    k_gather<<<(BOUT * SQ * DIM) / T, T>>>(Xout, mapping, out);
}

// round 10
// speedup vs baseline: 1.1718x; 1.1718x over previous
#include <cuda_runtime.h>
#include <cuda_fp16.h>
#include <math.h>
#include <stdint.h>

#define NN   8192
#define SQ   4
#define DIM  512
#define NH   4
#define DH   128
#define ET   73728
#define BOUT 128

// ---------------- scratch (device globals; no runtime alloc allowed) -------
__device__ float  g_node_raw[NN * 8];
__device__ float  g_node_pos[NN * DIM];
__device__ __half g_Xth[NN * DIM];
__device__ __half g_Xh [(size_t)SQ * NN * DIM];
__device__ float  g_Xout[(size_t)SQ * NN * DIM];
__device__ __half g_QKVh[(size_t)SQ * NN * 3 * DIM];
__device__ __half g_ehh [(size_t)ET * DIM];
__device__ __half g_e0h [(size_t)ET * DIM];
__device__ __half g_e1h [(size_t)SQ * ET * DIM];
__device__ __half g_Ew1h[(size_t)ET * 2 * DIM];
__device__ __half g_Ew2h[(size_t)SQ * ET * 2 * DIM];
__device__ float  g_logits[(size_t)SQ * ET * NH];
__device__ float  g_z[SQ * NN * NH];
__device__ __half g_Wpackth[2 * 3 * DIM * DIM];
__device__ __half g_wn2th[DIM * DIM];
__device__ __half g_wp2th[DIM * DIM];
__device__ __half g_WEth[2 * 2 * DIM * DIM];
// dst-CSR
__device__ int g_cnt[NN];
__device__ int g_cur[NN];
__device__ int g_off[NN + 1];
__device__ int g_eid[ET];

// ---------------- small utility kernels ------------------------------------
__global__ void kzeroi(int* __restrict__ p, int n) {
    int i = blockIdx.x * blockDim.x + threadIdx.x;
    if (i < n) p[i] = 0;
}

__global__ void kzero(float* __restrict__ p, size_t n) {
    size_t i = (size_t)blockIdx.x * blockDim.x + threadIdx.x;
    if (i < n) p[i] = 0.f;
}

__global__ void k_selfloop(const int* __restrict__ ei, const float* __restrict__ emb) {
    int e = blockIdx.x * blockDim.x + threadIdx.x;
    if (e >= ET) return;
    int s = ei[e], d = ei[ET + e];
    if (s == d) {
        #pragma unroll
        for (int r = 0; r < 8; r++)
            atomicAdd(&g_node_raw[s * 8 + r], emb[e * 8 + r]);
    }
}

__global__ void k_mlp1h(const float* __restrict__ in, const float* __restrict__ w1,
                        const float* __restrict__ b1, __half* __restrict__ out, int rows) {
    long long idx = (long long)blockIdx.x * blockDim.x + threadIdx.x;
    if (idx >= (long long)rows * DIM) return;
    int n = (int)(idx >> 9), j = (int)(idx & 511);
    const float* ip = in + (long long)n * 8;
    float acc = b1[j];
    #pragma unroll
    for (int r = 0; r < 8; r++) acc = fmaf(ip[r], w1[r * DIM + j], acc);
    out[idx] = __float2half_rn(fmaxf(acc, 0.f));
}

__global__ void k_add(const float* __restrict__ query, const float* __restrict__ npos,
                      __half* __restrict__ X) {
    size_t idx = (size_t)blockIdx.x * blockDim.x + threadIdx.x;
    if (idx >= (size_t)SQ * NN * DIM) return;
    int j = (int)(idx & 511);
    int n = (int)((idx >> 9) % NN);
    int s = (int)(idx / ((size_t)NN * DIM));
    X[idx] = __float2half_rn(query[(size_t)n * SQ * DIM + (size_t)s * DIM + j] +
                             npos[(size_t)n * DIM + j]);
}

__global__ void k_gather(const float* __restrict__ X, const int* __restrict__ mapping,
                         float* __restrict__ out) {
    int idx = blockIdx.x * blockDim.x + threadIdx.x;
    if (idx >= BOUT * SQ * DIM) return;
    int j = idx & 511;
    int s = (idx >> 9) & 3;
    int b = idx >> 11;
    out[idx] = X[((size_t)s * NN + mapping[b]) * DIM + j];
}

__global__ void k_transposeTh(const float* __restrict__ W, __half* __restrict__ Wt, int Nw) {
    int idx = blockIdx.x * blockDim.x + threadIdx.x;
    if (idx >= Nw * 512) return;
    int k = idx & 511;
    int n = idx >> 9;
    Wt[idx] = __float2half_rn(W[(size_t)k * Nw + n]);
}

__global__ void k_packwTh(const float* __restrict__ WQ, const float* __restrict__ WK,
                          const float* __restrict__ WV) {
    int idx = blockIdx.x * blockDim.x + threadIdx.x;
    if (idx >= 2 * 1536 * 512) return;
    int k = idx & 511;
    int n = (idx >> 9) % 1536;
    int l = idx / (1536 * 512);
    const float* W = (n < 512) ? WQ : ((n < 1024) ? WK : WV);
    int nn = n & 511;
    g_Wpackth[idx] = __float2half_rn(W[(size_t)l * 512 * 512 + (size_t)k * 512 + nn]);
}

// ---------------- CSR build --------------------------------------------------
__global__ void k_count(const int* __restrict__ dst) {
    int e = blockIdx.x * blockDim.x + threadIdx.x;
    if (e < ET) atomicAdd(&g_cnt[dst[e]], 1);
}

// single block, 1024 threads; 8 elements per thread
__global__ void k_scan() {
    __shared__ int part[1024];
    int tid = threadIdx.x;
    int base = tid * 8;
    int loc[8];
    int s = 0;
    #pragma unroll
    for (int i = 0; i < 8; i++) { loc[i] = s; s += g_cnt[base + i]; }
    part[tid] = s;
    __syncthreads();
    #pragma unroll
    for (int off = 1; off < 1024; off <<= 1) {
        int v = (tid >= off) ? part[tid - off] : 0;
        __syncthreads();
        part[tid] += v;
        __syncthreads();
    }
    int pre = (tid > 0) ? part[tid - 1] : 0;
    #pragma unroll
    for (int i = 0; i < 8; i++) g_off[base + i] = pre + loc[i];
    if (tid == 1023) g_off[NN] = part[1023];
}

__global__ void k_fill(const int* __restrict__ dst) {
    int e = blockIdx.x * blockDim.x + threadIdx.x;
    if (e >= ET) return;
    int d = dst[e];
    int pos = atomicAdd(&g_cur[d], 1);
    g_eid[g_off[d] + pos] = e;
}

// per-node insertion sort -> deterministic edge order
__global__ void k_sortseg() {
    int n = blockIdx.x * blockDim.x + threadIdx.x;
    if (n >= NN) return;
    int st = g_off[n], en = g_off[n + 1];
    for (int i = st + 1; i < en; i++) {
        int v = g_eid[i];
        int j = i - 1;
        while (j >= st && g_eid[j] > v) { g_eid[j + 1] = g_eid[j]; j--; }
        g_eid[j + 1] = v;
    }
}

// ---------------- fp16 tensor-core GEMM (ldmatrix fragments) ----------------
#define BKH     32
#define KTOT    512
#define KSTEPS  (KTOT / BKH)
#define STG     3
#define STRH    40
#define OP_HALVES (128 * STRH)
#define GEMM_SMEM (STG * 2 * OP_HALVES * 2)

__device__ __forceinline__ void cp16(uint32_t dst, const void* src) {
    asm volatile("cp.async.cg.shared.global [%0], [%1], 16;\n" :: "r"(dst), "l"(src));
}
__device__ __forceinline__ void cp_commit() { asm volatile("cp.async.commit_group;\n"); }
__device__ __forceinline__ void cp_wait1()  { asm volatile("cp.async.wait_group 1;\n"); }

__device__ __forceinline__ void ldsm4(uint32_t& r0, uint32_t& r1, uint32_t& r2,
                                      uint32_t& r3, uint32_t addr) {
    asm volatile("ldmatrix.sync.aligned.m8n8.x4.shared.b16 {%0,%1,%2,%3}, [%4];"
                 : "=r"(r0), "=r"(r1), "=r"(r2), "=r"(r3) : "r"(addr));
}

__device__ __forceinline__ void mma_f16(float& c0, float& c1, float& c2, float& c3,
                                        uint32_t a0, uint32_t a1, uint32_t a2, uint32_t a3,
                                        uint32_t b0, uint32_t b1) {
    asm volatile("mma.sync.aligned.m16n8k16.row.col.f32.f16.f16.f32 "
                 "{%0,%1,%2,%3}, {%4,%5,%6,%7}, {%8,%9}, {%0,%1,%2,%3};\n"
                 : "+f"(c0), "+f"(c1), "+f"(c2), "+f"(c3)
                 : "r"(a0), "r"(a1), "r"(a2), "r"(a3), "r"(b0), "r"(b1));
}

__global__ void __launch_bounds__(256, 2)
gemm_h(const __half* __restrict__ A, const __half* __restrict__ Bt,
       const float* __restrict__ bias, void* __restrict__ Cout,
       int M, int N, int halfOut) {
    extern __shared__ __half sh[];
    __half* Abase = sh;
    __half* Bbase = sh + STG * OP_HALVES;

    const int tid  = threadIdx.x;
    const int lane = tid & 31;
    const int warp = tid >> 5;
    const int wm = warp & 1;
    const int wn = warp >> 1;
    const int g  = lane >> 2;
    const int t  = lane & 3;

    const long long bRow = (long long)blockIdx.y * 128;
    const long long bCol = (long long)blockIdx.x * 128;

    int rowL[2], cL[2];
    #pragma unroll
    for (int i = 0; i < 2; i++) {
        int ch = tid * 2 + i;
        rowL[i] = ch >> 2;
        cL[i]   = ch & 3;
    }
    const uint32_t suA = (uint32_t)__cvta_generic_to_shared(Abase);
    const uint32_t suB = (uint32_t)__cvta_generic_to_shared(Bbase);
    uint32_t aD[2], bD[2];
    #pragma unroll
    for (int i = 0; i < 2; i++) {
        aD[i] = suA + (uint32_t)(rowL[i] * STRH + cL[i] * 8) * 2u;
        bD[i] = suB + (uint32_t)(rowL[i] * STRH + cL[i] * 8) * 2u;
    }
    const __half* Ag[2];
    const __half* Bg[2];
    #pragma unroll
    for (int i = 0; i < 2; i++) {
        Ag[i] = A  + (bRow + rowL[i]) * (long long)KTOT + cL[i] * 8;
        Bg[i] = Bt + (bCol + rowL[i]) * (long long)KTOT + cL[i] * 8;
    }

    const uint32_t laneAoff = (uint32_t)(((lane & 7) + ((lane >> 3) & 1) * 8) * STRH
                                         + (lane >> 4) * 8);
    const uint32_t laneBoff = (uint32_t)(((lane & 7) + (lane >> 4) * 8) * STRH
                                         + ((lane >> 3) & 1) * 8);

    float acc[4][4][4];
    #pragma unroll
    for (int mt = 0; mt < 4; mt++)
        #pragma unroll
        for (int nt = 0; nt < 4; nt++)
            #pragma unroll
            for (int q = 0; q < 4; q++) acc[mt][nt][q] = 0.f;

    #pragma unroll
    for (int s = 0; s < 2; s++) {
        #pragma unroll
        for (int i = 0; i < 2; i++) {
            cp16(aD[i] + (uint32_t)(s * OP_HALVES * 2), Ag[i] + s * BKH);
            cp16(bD[i] + (uint32_t)(s * OP_HALVES * 2), Bg[i] + s * BKH);
        }
        cp_commit();
    }

    for (int kt = 0; kt < KSTEPS; kt++) {
        cp_wait1();
        __syncthreads();

        if (kt + 2 < KSTEPS) {
            const int st = (kt + 2) % STG;
            #pragma unroll
            for (int i = 0; i < 2; i++) {
                cp16(aD[i] + (uint32_t)(st * OP_HALVES * 2), Ag[i] + (kt + 2) * BKH);
                cp16(bD[i] + (uint32_t)(st * OP_HALVES * 2), Bg[i] + (kt + 2) * BKH);
            }
        }
        cp_commit();

        const uint32_t Ab = suA + (uint32_t)((kt % STG) * OP_HALVES) * 2u;
        const uint32_t Bb = suB + (uint32_t)((kt % STG) * OP_HALVES) * 2u;

        #pragma unroll
        for (int kk = 0; kk < BKH; kk += 16) {
            uint32_t af[4][4], bf[4][2];
            #pragma unroll
            for (int mt = 0; mt < 4; mt++) {
                uint32_t addr = Ab + 2u * (laneAoff + (uint32_t)((wm * 64 + mt * 16) * STRH + kk));
                ldsm4(af[mt][0], af[mt][1], af[mt][2], af[mt][3], addr);
            }
            #pragma unroll
            for (int p = 0; p < 2; p++) {
                uint32_t addr = Bb + 2u * (laneBoff + (uint32_t)((wn * 32 + p * 16) * STRH + kk));
                ldsm4(bf[2 * p][0], bf[2 * p][1], bf[2 * p + 1][0], bf[2 * p + 1][1], addr);
            }
            #pragma unroll
            for (int mt = 0; mt < 4; mt++)
                #pragma unroll
                for (int nt = 0; nt < 4; nt++)
                    mma_f16(acc[mt][nt][0], acc[mt][nt][1], acc[mt][nt][2], acc[mt][nt][3],
                            af[mt][0], af[mt][1], af[mt][2], af[mt][3],
                            bf[nt][0], bf[nt][1]);
        }
        __syncthreads();
    }

    #pragma unroll
    for (int mt = 0; mt < 4; mt++) {
        #pragma unroll
        for (int nt = 0; nt < 4; nt++) {
            long long row0 = bRow + wm * 64 + mt * 16 + g;
            long long col  = bCol + wn * 32 + nt * 8 + t * 2;
            float b0 = 0.f, b1 = 0.f;
            if (bias) { b0 = bias[col]; b1 = bias[col + 1]; }
            float v00 = acc[mt][nt][0] + b0, v01 = acc[mt][nt][1] + b1;
            float v10 = acc[mt][nt][2] + b0, v11 = acc[mt][nt][3] + b1;
            if (halfOut) {
                __half2* C = (__half2*)Cout;
                C[(row0 * N + col) >> 1]       = __floats2half2_rn(v00, v01);
                C[((row0 + 8) * N + col) >> 1] = __floats2half2_rn(v10, v11);
            } else {
                float* C = (float*)Cout;
                *(float2*)(C + row0 * N + col)       = make_float2(v00, v01);
                *(float2*)(C + (row0 + 8) * N + col) = make_float2(v10, v11);
            }
        }
    }
}

// ---------------- layer-0 edge kernel: warp per (e,h), loops s --------------
__global__ void k_edge0(const __half* __restrict__ QKV,
                        const int* __restrict__ src, const int* __restrict__ dst,
                        const __half* __restrict__ Ew,
                        const float* __restrict__ aw, __half* __restrict__ e_out) {
    int w = (blockIdx.x * blockDim.x + threadIdx.x) >> 5;
    int lane = threadIdx.x & 31;
    if (w >= ET * NH) return;
    int e = w >> 2, h = w & 3;
    int sn = src[e], dn = dst[e];

    const __half2* ewp = (const __half2*)(Ew + (size_t)e * (2 * DIM) + h * 256);
    __half2 ew[2], eb[2];
    float a0[2], a1[2];
    #pragma unroll
    for (int i = 0; i < 2; i++) {
        int dd = lane + 32 * i;
        ew[i] = ewp[dd];
        eb[i] = ewp[dd + 64];
        a0[i] = aw[h * DH + 2 * dd];
        a1[i] = aw[h * DH + 2 * dd + 1];
    }

    #pragma unroll
    for (int s = 0; s < SQ; s++) {
        const __half2* qp = (const __half2*)(QKV + ((size_t)s * NN + dn) * (3 * DIM) + h * DH);
        const __half2* kp = (const __half2*)(QKV + ((size_t)s * NN + sn) * (3 * DIM) + DIM + h * DH);
        __half2* op = (__half2*)(e_out + ((size_t)s * ET + e) * DIM + h * DH);
        float lg = 0.f;
        #pragma unroll
        for (int i = 0; i < 2; i++) {
            int dd = lane + 32 * i;
            float2 kq = __half22float2(__hadd2(kp[dd], qp[dd]));
            float2 ewf = __half22float2(ew[i]);
            float2 ebf = __half22float2(eb[i]);
            float t0 = kq.x * ewf.x, t1 = kq.y * ewf.y;
            float s0 = (t0 >= 0.f) ? sqrtf(t0) : -sqrtf(-t0);
            float s1 = (t1 >= 0.f) ? sqrtf(t1) : -sqrtf(-t1);
            s0 = fmaxf(s0 + ebf.x, 0.f);
            s1 = fmaxf(s1 + ebf.y, 0.f);
            op[dd] = __floats2half2_rn(s0, s1);
            lg = fmaf(s0, a0[i], lg);
            lg = fmaf(s1, a1[i], lg);
        }
        #pragma unroll
        for (int off = 16; off; off >>= 1) lg += __shfl_xor_sync(0xffffffffu, lg, off);
        if (lane == 0) g_logits[((size_t)s * ET + e) * NH + h] = lg;
    }
}

// ---------------- layer-1 edge kernel: warp per (s,e,h) ----------------------
__global__ void k_edge1(const __half* __restrict__ QKV,
                        const int* __restrict__ src, const int* __restrict__ dst,
                        const __half* __restrict__ Ew, const float* __restrict__ aw) {
    long long w = ((long long)blockIdx.x * blockDim.x + threadIdx.x) >> 5;
    int lane = threadIdx.x & 31;
    if (w >= (long long)SQ * ET * NH) return;
    int s = (int)(w / (ET * NH));
    int r = (int)(w % (ET * NH));
    int e = r >> 2, h = r & 3;
    int sn = src[e], dn = dst[e];
    const __half2* qp  = (const __half2*)(QKV + ((size_t)s * NN + dn) * (3 * DIM) + h * DH);
    const __half2* kp  = (const __half2*)(QKV + ((size_t)s * NN + sn) * (3 * DIM) + DIM + h * DH);
    const __half2* ewp = (const __half2*)(Ew + ((size_t)s * ET + e) * (2 * DIM) + h * 256);
    float lg = 0.f;
    #pragma unroll
    for (int i = 0; i < 2; i++) {
        int dd = lane + 32 * i;
        float2 kq = __half22float2(__hadd2(kp[dd], qp[dd]));
        float2 ewf = __half22float2(ewp[dd]);
        float2 ebf = __half22float2(ewp[dd + 64]);
        float t0 = kq.x * ewf.x, t1 = kq.y * ewf.y;
        float s0 = (t0 >= 0.f) ? sqrtf(t0) : -sqrtf(-t0);
        float s1 = (t1 >= 0.f) ? sqrtf(t1) : -sqrtf(-t1);
        s0 = fmaxf(s0 + ebf.x, 0.f);
        s1 = fmaxf(s1 + ebf.y, 0.f);
        lg = fmaf(s0, aw[h * DH + 2 * dd], lg);
        lg = fmaf(s1, aw[h * DH + 2 * dd + 1], lg);
    }
    #pragma unroll
    for (int off = 16; off; off >>= 1) lg += __shfl_xor_sync(0xffffffffu, lg, off);
    if (lane == 0) g_logits[((size_t)s * ET + e) * NH + h] = lg;
}

// ---------------- softmax via CSR: thread per (s,n,h) ------------------------
// overwrites logits[e] with exp(lg-m); stores z.
__global__ void k_alpha() {
    int i = blockIdx.x * blockDim.x + threadIdx.x;
    if (i >= SQ * NN * NH) return;
    int h = i & 3;
    int n = (i >> 2) % NN;
    int s = (i >> 2) / NN;
    int st = g_off[n], en = g_off[n + 1];
    float m = -1e30f;
    for (int j = st; j < en; j++) {
        float lg = g_logits[((size_t)s * ET + g_eid[j]) * NH + h];
        m = fmaxf(m, lg);
    }
    float z = 0.f;
    for (int j = st; j < en; j++) {
        size_t li = ((size_t)s * ET + g_eid[j]) * NH + h;
        float wv = expf(g_logits[li] - m);
        g_logits[li] = wv;
        z += wv;
    }
    g_z[(s * NN + n) * NH + h] = z;
}

// ---------------- message gather via CSR: warp per (s,n,h) -------------------
__global__ void k_msg_csr(const __half* __restrict__ QKV, const int* __restrict__ src,
                          __half* __restrict__ outH, float* __restrict__ outF) {
    int w = (blockIdx.x * blockDim.x + threadIdx.x) >> 5;
    int lane = threadIdx.x & 31;
    if (w >= SQ * NN * NH) return;
    int h = w & 3;
    int n = (w >> 2) % NN;
    int s = (w >> 2) / NN;
    int st = g_off[n], en = g_off[n + 1];
    float inv = 1.f / (g_z[(s * NN + n) * NH + h] + 1e-16f);

    float acc0x = 0.f, acc0y = 0.f, acc1x = 0.f, acc1y = 0.f;
    for (int j = st; j < en; j++) {
        int e = g_eid[j];
        float wv = g_logits[((size_t)s * ET + e) * NH + h] * inv;
        int sn = src[e];
        const __half2* vp = (const __half2*)(QKV + ((size_t)s * NN + sn) * (3 * DIM)
                                             + 2 * DIM + h * DH);
        float2 v0 = __half22float2(vp[lane]);
        float2 v1 = __half22float2(vp[lane + 32]);
        acc0x = fmaf(v0.x, wv, acc0x);
        acc0y = fmaf(v0.y, wv, acc0y);
        acc1x = fmaf(v1.x, wv, acc1x);
        acc1y = fmaf(v1.y, wv, acc1y);
    }
    size_t base = ((size_t)s * NN + n) * DIM + h * DH;
    if (outH) {
        __half2* op = (__half2*)(outH + base);
        op[lane]      = __floats2half2_rn(acc0x, acc0y);
        op[lane + 32] = __floats2half2_rn(acc1x, acc1y);
    } else {
        float* op = outF + base;
        op[2 * lane]          = acc0x;
        op[2 * lane + 1]      = acc0y;
        op[2 * (lane + 32)]     = acc1x;
        op[2 * (lane + 32) + 1] = acc1y;
    }
}

// ---------------- host orchestration ---------------------------------------
extern "C" void kernel_launch(void* const* d_in, const int* in_sizes, int n_in,
                              void* d_out, int out_size) {
    const float* query   = (const float*)d_in[0];
    const int*   ei      = (const int*)  d_in[1];
    const int*   mapping = (const int*)  d_in[2];
    const float* emb     = (const float*)d_in[3];
    const float* wn_w1 = (const float*)d_in[5];
    const float* wn_b1 = (const float*)d_in[6];
    const float* wn_w2 = (const float*)d_in[7];
    const float* wn_b2 = (const float*)d_in[8];
    const float* wp_w1 = (const float*)d_in[9];
    const float* wp_b1 = (const float*)d_in[10];
    const float* wp_w2 = (const float*)d_in[11];
    const float* wp_b2 = (const float*)d_in[12];
    const float* WQ    = (const float*)d_in[13];
    const float* WK    = (const float*)d_in[14];
    const float* WV    = (const float*)d_in[15];
    const float* WE    = (const float*)d_in[16];
    const float* bE    = (const float*)d_in[17];
    const float* Aw    = (const float*)d_in[18];
    float* out = (float*)d_out;

    float  *node_raw, *node_pos, *Xout;
    __half *Xth, *Xh, *QKVh, *ehh, *e0h, *e1h, *Ew1h, *Ew2h;
    __half *Wpackth, *wn2th, *wp2th, *WEth;
    int *cnt, *cur;
    cudaGetSymbolAddress((void**)&node_raw, g_node_raw);
    cudaGetSymbolAddress((void**)&node_pos, g_node_pos);
    cudaGetSymbolAddress((void**)&Xth,  g_Xth);
    cudaGetSymbolAddress((void**)&Xh,   g_Xh);
    cudaGetSymbolAddress((void**)&Xout, g_Xout);
    cudaGetSymbolAddress((void**)&QKVh, g_QKVh);
    cudaGetSymbolAddress((void**)&ehh,  g_ehh);
    cudaGetSymbolAddress((void**)&e0h,  g_e0h);
    cudaGetSymbolAddress((void**)&e1h,  g_e1h);
    cudaGetSymbolAddress((void**)&Ew1h, g_Ew1h);
    cudaGetSymbolAddress((void**)&Ew2h, g_Ew2h);
    cudaGetSymbolAddress((void**)&Wpackth, g_Wpackth);
    cudaGetSymbolAddress((void**)&wn2th, g_wn2th);
    cudaGetSymbolAddress((void**)&wp2th, g_wp2th);
    cudaGetSymbolAddress((void**)&WEth,  g_WEth);
    cudaGetSymbolAddress((void**)&cnt, g_cnt);
    cudaGetSymbolAddress((void**)&cur, g_cur);

    cudaFuncSetAttribute(gemm_h, cudaFuncAttributeMaxDynamicSharedMemorySize, GEMM_SMEM);

    const int* srcp = ei;
    const int* dstp = ei + ET;
    const int T = 256;

    // ---- CSR build (edges fixed across layers/positions) ----
    kzeroi<<<(NN + T - 1) / T, T>>>(cnt, NN);
    kzeroi<<<(NN + T - 1) / T, T>>>(cur, NN);
    k_count<<<(ET + T - 1) / T, T>>>(dstp);
    k_scan<<<1, 1024>>>();
    k_fill<<<(ET + T - 1) / T, T>>>(dstp);
    k_sortseg<<<(NN + T - 1) / T, T>>>();

    // ---- fp16 weight packs (tiny) ----
    k_transposeTh<<<(512 * 512) / T, T>>>(wn_w2, wn2th, 512);
    k_transposeTh<<<(512 * 512) / T, T>>>(wp_w2, wp2th, 512);
    k_transposeTh<<<(1024 * 512) / T, T>>>(WE, WEth, 1024);
    k_transposeTh<<<(1024 * 512) / T, T>>>(WE + 512 * 1024, WEth + 1024 * 512, 1024);
    k_packwTh<<<(2 * 1536 * 512) / T, T>>>(WQ, WK, WV);

    // ---- position-invariant precompute ----
    kzero<<<(NN * 8 + T - 1) / T, T>>>(node_raw, NN * 8);
    k_selfloop<<<(ET + T - 1) / T, T>>>(ei, emb);
    k_mlp1h<<<(NN * DIM) / T, T>>>(node_raw, wn_w1, wn_b1, Xth, NN);
    gemm_h<<<dim3(DIM / 128, NN / 128), T, GEMM_SMEM>>>(Xth, wn2th, wn_b2, node_pos,
                                                        NN, DIM, 0);
    k_mlp1h<<<(ET * DIM) / T, T>>>(emb, wp_w1, wp_b1, ehh, ET);
    gemm_h<<<dim3(DIM / 128, ET / 128), T, GEMM_SMEM>>>(ehh, wp2th, wp_b2, e0h,
                                                        ET, DIM, 1);
    gemm_h<<<dim3((2 * DIM) / 128, ET / 128), T, GEMM_SMEM>>>(e0h, WEth, bE, Ew1h,
                                                              ET, 2 * DIM, 1);

    // ---- batched positions ----
    k_add<<<(SQ * NN * DIM) / T, T>>>(query, node_pos, Xh);

    const int snhThreadBlocks = (SQ * NN * NH + T - 1) / T;
    const int snhWarpBlocks   = (SQ * NN * NH * 32) / T;

    // ======== layer 0 ========
    gemm_h<<<dim3((3 * DIM) / 128, (SQ * NN) / 128), T, GEMM_SMEM>>>(
        Xh, Wpackth, nullptr, QKVh, SQ * NN, 3 * DIM, 1);
    k_edge0<<<(ET * NH * 32) / T, T>>>(QKVh, srcp, dstp, Ew1h, Aw, e1h);
    k_alpha<<<snhThreadBlocks, T>>>();
    k_msg_csr<<<snhWarpBlocks, T>>>(QKVh, srcp, Xh, nullptr);

    // ======== layer 1 ========
    gemm_h<<<dim3((3 * DIM) / 128, (SQ * NN) / 128), T, GEMM_SMEM>>>(
        Xh, Wpackth + (size_t)1536 * 512, nullptr, QKVh, SQ * NN, 3 * DIM, 1);
    gemm_h<<<dim3((2 * DIM) / 128, (SQ * ET) / 128), T, GEMM_SMEM>>>(
        e1h, WEth + 1024 * 512, bE + 2 * DIM, Ew2h, SQ * ET, 2 * DIM, 1);
    k_edge1<<<((long long)SQ * ET * NH * 32) / T, T>>>(QKVh, srcp, dstp, Ew2h, Aw + DIM);
    k_alpha<<<snhThreadBlocks, T>>>();
    k_msg_csr<<<snhWarpBlocks, T>>>(QKVh, srcp, nullptr, Xout);

    k_gather<<<(BOUT * SQ * DIM) / T, T>>>(Xout, mapping, out);
}